// round 1
// baseline (speedup 1.0000x reference)
#include <cuda_runtime.h>

// Problem shape constants (fixed by the benchmark; runtime values derived from
// in_sizes are used for loop bounds, these bound the static scratch buffers).
#define MAXN 20000
#define MAXE 320000
#define FIN  128
#define HID  64
#define MAXB 8

// ---------------- static device scratch (allocation-free rule) ----------------
__device__ float g_hw[(size_t)MAXN * MAXB * HID];   // transformed features, node-major [n][b*64]
__device__ float g_h1[(size_t)MAXN * MAXB * HID];   // layer-1 activations, node-major
__device__ int   g_cnt[MAXN];                        // in-degree counts
__device__ int   g_offs[MAXN + 1];                   // CSR offsets (by dst)
__device__ int   g_cursor[MAXN];                     // CSR fill cursors
__device__ float g_dis[MAXN];                        // deg^{-1/2}
__device__ int   g_csr_src[MAXE];                    // CSR: src node per slot
__device__ float g_csr_w[MAXE];                      // CSR: edge norm per slot
__device__ float g_partial[MAXB * 64];               // binned pooled partials

// ---------------- init: zero counters + partials ----------------
__global__ void k_init(int N) {
    int i = blockIdx.x * blockDim.x + threadIdx.x;
    if (i < N) g_cnt[i] = 0;
    if (i < MAXB * 64) g_partial[i] = 0.0f;
}

// ---------------- in-degree count (dst row of edge_index) ----------------
__global__ void k_count(const int* __restrict__ ei, int E) {
    int e = blockIdx.x * blockDim.x + threadIdx.x;
    if (e < E) atomicAdd(&g_cnt[ei[E + e]], 1);
}

// ---------------- single-block scan -> offsets, cursors, dis ----------------
__global__ void k_scan(int N) {
    __shared__ int ss[1024];
    int tid = threadIdx.x;
    int CH = (N + 1023) >> 10;
    int base = tid * CH;
    int s = 0;
    for (int j = 0; j < CH; j++) {
        int i = base + j;
        if (i < N) s += g_cnt[i];
    }
    ss[tid] = s;
    __syncthreads();
    for (int off = 1; off < 1024; off <<= 1) {
        int v = (tid >= off) ? ss[tid - off] : 0;
        __syncthreads();
        ss[tid] += v;
        __syncthreads();
    }
    int run = (tid == 0) ? 0 : ss[tid - 1];
    for (int j = 0; j < CH; j++) {
        int i = base + j;
        if (i < N) {
            g_offs[i] = run;
            g_cursor[i] = run;
            g_dis[i] = rsqrtf(1.0f + (float)g_cnt[i]);
            run += g_cnt[i];
        }
    }
    if (tid == 0) g_offs[N] = ss[1023];
}

// ---------------- CSR fill: slot per edge grouped by dst ----------------
__global__ void k_csr(const int* __restrict__ ei, int E) {
    int e = blockIdx.x * blockDim.x + threadIdx.x;
    if (e < E) {
        int s = ei[e];
        int d = ei[E + e];
        int pos = atomicAdd(&g_cursor[d], 1);
        g_csr_src[pos] = s;
        g_csr_w[pos] = g_dis[s] * g_dis[d];
    }
}

// ---------------- tiled GEMM: out[row] = in[row] @ W  (HID=64 outputs) ----------
// SRC=0: read from `in` param (x, batch-major rows r = b*N+n, stride KDIM)
// SRC=1: read from g_h1 (node-major rows, stride KDIM=64)
// TROUT: remap output row r=b*N+n -> node-major n*B+b. Output always g_hw.
template <int KDIM, bool TROUT, int SRC>
__global__ void __launch_bounds__(256) k_gemm(const float* __restrict__ in,
                                              const float* __restrict__ Wm,
                                              int nrows, int Nn, int Bsz) {
    __shared__ float ws[KDIM * HID];
    __shared__ float xs[32 * KDIM];
    int tid = threadIdx.x;
    int r0 = blockIdx.x * 32;

    for (int i = tid; i < KDIM * HID; i += 256) ws[i] = Wm[i];

    const float* src = (SRC == 1) ? g_h1 : in;
    const int v4 = KDIM / 4;
    for (int idx = tid; idx < 32 * v4; idx += 256) {
        int i = idx / v4;
        int kk = (idx % v4) * 4;
        int r = r0 + i;
        float4 v = make_float4(0.f, 0.f, 0.f, 0.f);
        if (r < nrows) v = *(const float4*)(src + (size_t)r * KDIM + kk);
        *(float4*)(xs + i * KDIM + kk) = v;
    }
    __syncthreads();

    int tx = tid & 15, ty = tid >> 4;
    float acc[2][4];
#pragma unroll
    for (int j = 0; j < 2; j++)
#pragma unroll
        for (int o = 0; o < 4; o++) acc[j][o] = 0.f;

#pragma unroll 8
    for (int k = 0; k < KDIM; k++) {
        float4 wv = *(const float4*)(ws + k * HID + tx * 4);
#pragma unroll
        for (int j = 0; j < 2; j++) {
            float xv = xs[(ty * 2 + j) * KDIM + k];
            acc[j][0] = fmaf(xv, wv.x, acc[j][0]);
            acc[j][1] = fmaf(xv, wv.y, acc[j][1]);
            acc[j][2] = fmaf(xv, wv.z, acc[j][2]);
            acc[j][3] = fmaf(xv, wv.w, acc[j][3]);
        }
    }
#pragma unroll
    for (int j = 0; j < 2; j++) {
        int r = r0 + ty * 2 + j;
        if (r < nrows) {
            size_t orow = TROUT ? ((size_t)(r % Nn) * Bsz + (size_t)(r / Nn)) : (size_t)r;
            *(float4*)(g_hw + orow * HID + tx * 4) =
                make_float4(acc[j][0], acc[j][1], acc[j][2], acc[j][3]);
        }
    }
}

// ---------------- layer-1 aggregation + bias + relu -> g_h1 ----------------
// One block per dst node; 256 threads cover the 512 (b,h) floats as float2.
__global__ void __launch_bounds__(256) k_agg1(const float* __restrict__ bias, int Bsz) {
    int node = blockIdx.x;
    int f = threadIdx.x * 2;
    int rowlen = Bsz * HID;
    if (f >= rowlen) return;
    int h = f & (HID - 1);
    float d = g_dis[node];
    float sn = d * d;
    size_t base = (size_t)node * rowlen;
    float2 v = *(const float2*)(g_hw + base + f);
    float2 acc = make_float2(bias[h] + v.x * sn, bias[h + 1] + v.y * sn);

    int e = g_offs[node], e1 = g_offs[node + 1];
    for (; e + 1 < e1; e += 2) {
        int s0 = g_csr_src[e];
        int s1 = g_csr_src[e + 1];
        float w0 = g_csr_w[e];
        float w1 = g_csr_w[e + 1];
        float2 m0 = *(const float2*)(g_hw + (size_t)s0 * rowlen + f);
        float2 m1 = *(const float2*)(g_hw + (size_t)s1 * rowlen + f);
        acc.x = fmaf(w0, m0.x, acc.x);
        acc.y = fmaf(w0, m0.y, acc.y);
        acc.x = fmaf(w1, m1.x, acc.x);
        acc.y = fmaf(w1, m1.y, acc.y);
    }
    if (e < e1) {
        int s0 = g_csr_src[e];
        float w0 = g_csr_w[e];
        float2 m0 = *(const float2*)(g_hw + (size_t)s0 * rowlen + f);
        acc.x = fmaf(w0, m0.x, acc.x);
        acc.y = fmaf(w0, m0.y, acc.y);
    }
    acc.x = fmaxf(acc.x, 0.f);
    acc.y = fmaxf(acc.y, 0.f);
    *(float2*)(g_h1 + base + f) = acc;
}

// ---------------- layer-2 aggregation + relu, fused with fc_w dot + pooling ----
// Never materializes h2: each warp owns one batch b and reduces its node
// contribution, binning by node&63 to limit same-address atomic pressure.
__global__ void __launch_bounds__(256) k_agg2(const float* __restrict__ bias,
                                              const float* __restrict__ fcw, int Bsz) {
    int node = blockIdx.x;
    int f = threadIdx.x * 2;
    int rowlen = Bsz * HID;
    if (f >= rowlen) return;
    int h = f & (HID - 1);
    float d = g_dis[node];
    float sn = d * d;
    size_t base = (size_t)node * rowlen;
    float2 v = *(const float2*)(g_hw + base + f);
    float2 acc = make_float2(bias[h] + v.x * sn, bias[h + 1] + v.y * sn);

    int e = g_offs[node], e1 = g_offs[node + 1];
    for (; e + 1 < e1; e += 2) {
        int s0 = g_csr_src[e];
        int s1 = g_csr_src[e + 1];
        float w0 = g_csr_w[e];
        float w1 = g_csr_w[e + 1];
        float2 m0 = *(const float2*)(g_hw + (size_t)s0 * rowlen + f);
        float2 m1 = *(const float2*)(g_hw + (size_t)s1 * rowlen + f);
        acc.x = fmaf(w0, m0.x, acc.x);
        acc.y = fmaf(w0, m0.y, acc.y);
        acc.x = fmaf(w1, m1.x, acc.x);
        acc.y = fmaf(w1, m1.y, acc.y);
    }
    if (e < e1) {
        int s0 = g_csr_src[e];
        float w0 = g_csr_w[e];
        float2 m0 = *(const float2*)(g_hw + (size_t)s0 * rowlen + f);
        acc.x = fmaf(w0, m0.x, acc.x);
        acc.y = fmaf(w0, m0.y, acc.y);
    }
    acc.x = fmaxf(acc.x, 0.f);
    acc.y = fmaxf(acc.y, 0.f);

    // fc dot-product contribution for this node, this batch
    float c = acc.x * fcw[h] + acc.y * fcw[h + 1];
#pragma unroll
    for (int o = 16; o; o >>= 1) c += __shfl_xor_sync(0xffffffffu, c, o);
    if ((threadIdx.x & 31) == 0) {
        int b = threadIdx.x >> 5;  // warp == batch (f/64 == tid/32)
        atomicAdd(&g_partial[b * 64 + (node & 63)], c);
    }
}

// ---------------- final: reduce bins, add additional-feature term ----------------
__global__ void k_final(float* __restrict__ out, const float* __restrict__ add,
                        const float* __restrict__ fcw, const float* __restrict__ fcb,
                        int N, int Bsz) {
    int b = threadIdx.x >> 5;
    int lane = threadIdx.x & 31;
    if (b < Bsz) {
        float s = g_partial[b * 64 + lane] + g_partial[b * 64 + 32 + lane];
#pragma unroll
        for (int o = 16; o; o >>= 1) s += __shfl_xor_sync(0xffffffffu, s, o);
        if (lane == 0)
            out[b] = s * (1.0f / (float)N) + add[b] * fcw[HID] + fcb[0];
    }
}

// ---------------- launch ----------------
extern "C" void kernel_launch(void* const* d_in, const int* in_sizes, int n_in,
                              void* d_out, int out_size) {
    const float* x   = (const float*)d_in[0];
    const float* add = (const float*)d_in[1];
    const int*   ei  = (const int*)d_in[2];
    const float* W1  = (const float*)d_in[3];
    const float* b1  = (const float*)d_in[4];
    const float* W2  = (const float*)d_in[5];
    const float* b2  = (const float*)d_in[6];
    const float* fcw = (const float*)d_in[7];
    const float* fcb = (const float*)d_in[8];
    float* out = (float*)d_out;

    int B = in_sizes[1];                 // additional_features is [B,1]
    int E = in_sizes[2] / 2;             // edge_index is [2,E]
    int N = in_sizes[0] / (B * FIN);     // x is [B,N,FIN]
    int rows = B * N;

    k_init<<<(N + 255) / 256, 256>>>(N);
    k_count<<<(E + 255) / 256, 256>>>(ei, E);
    k_scan<<<1, 1024>>>(N);
    k_csr<<<(E + 255) / 256, 256>>>(ei, E);

    // layer 1: hw = x @ W1 (node-major output), then CSR aggregate + relu
    k_gemm<FIN, true, 0><<<(rows + 31) / 32, 256>>>(x, W1, rows, N, B);
    k_agg1<<<N, 256>>>(b1, B);

    // layer 2: hw = h1 @ W2, then aggregate fused with fc-dot + mean pool
    k_gemm<HID, false, 1><<<(rows + 31) / 32, 256>>>(x, W2, rows, N, B);
    k_agg2<<<N, 256>>>(b2, fcw, B);

    k_final<<<1, 256>>>(out, add, fcw, fcb, N, B);
}

// round 2
// speedup vs baseline: 1.2115x; 1.2115x over previous
#include <cuda_runtime.h>
#include <cuda_fp16.h>

#define MAXN 20000
#define MAXE 320000
#define FIN  128
#define HID  64
#define MAXB 8

// ---------------- static device scratch (allocation-free rule) ----------------
__device__ __half g_hw[(size_t)MAXN * MAXB * HID];  // transformed features, node-major [n][b*64], fp16
__device__ __half g_h1[(size_t)MAXN * MAXB * HID];  // layer-1 activations, node-major, fp16
__device__ int    g_cnt[MAXN];
__device__ int    g_offs[MAXN + 1];
__device__ int    g_cursor[MAXN];
__device__ float  g_dis[MAXN];
__device__ int    g_csr_src[MAXE];
__device__ float  g_csr_w[MAXE];
__device__ float  g_partial[MAXB * 64];

// ---------------- packed f32x2 helpers (FFMA2) ----------------
__device__ __forceinline__ void ffma2(unsigned long long& d, unsigned long long a,
                                      unsigned long long b) {
    asm("fma.rn.f32x2 %0, %1, %2, %0;" : "+l"(d) : "l"(a), "l"(b));
}
__device__ __forceinline__ unsigned long long dup2(float v) {
    unsigned long long r;
    asm("mov.b64 %0, {%1, %1};" : "=l"(r) : "f"(v));
    return r;
}
__device__ __forceinline__ float2 unpk(unsigned long long v) {
    float2 f;
    asm("mov.b64 {%0, %1}, %2;" : "=f"(f.x), "=f"(f.y) : "l"(v));
    return f;
}

// ---------------- init ----------------
__global__ void k_init(int N) {
    int i = blockIdx.x * blockDim.x + threadIdx.x;
    if (i < N) g_cnt[i] = 0;
    if (i < MAXB * 64) g_partial[i] = 0.0f;
}

// ---------------- in-degree count ----------------
__global__ void k_count(const int* __restrict__ ei, int E) {
    int e = blockIdx.x * blockDim.x + threadIdx.x;
    if (e < E) atomicAdd(&g_cnt[ei[E + e]], 1);
}

// ---------------- single-block scan -> offsets, cursors, dis ----------------
__global__ void k_scan(int N) {
    __shared__ int ss[1024];
    int tid = threadIdx.x;
    int CH = (N + 1023) >> 10;
    int base = tid * CH;
    int s = 0;
    for (int j = 0; j < CH; j++) {
        int i = base + j;
        if (i < N) s += g_cnt[i];
    }
    ss[tid] = s;
    __syncthreads();
    for (int off = 1; off < 1024; off <<= 1) {
        int v = (tid >= off) ? ss[tid - off] : 0;
        __syncthreads();
        ss[tid] += v;
        __syncthreads();
    }
    int run = (tid == 0) ? 0 : ss[tid - 1];
    for (int j = 0; j < CH; j++) {
        int i = base + j;
        if (i < N) {
            g_offs[i] = run;
            g_cursor[i] = run;
            g_dis[i] = rsqrtf(1.0f + (float)g_cnt[i]);
            run += g_cnt[i];
        }
    }
    if (tid == 0) g_offs[N] = ss[1023];
}

// ---------------- CSR fill ----------------
__global__ void k_csr(const int* __restrict__ ei, int E) {
    int e = blockIdx.x * blockDim.x + threadIdx.x;
    if (e < E) {
        int s = ei[e];
        int d = ei[E + e];
        int pos = atomicAdd(&g_cursor[d], 1);
        g_csr_src[pos] = s;
        g_csr_w[pos] = g_dis[s] * g_dis[d];
    }
}

// ---------------- GEMM1: hw = x @ W1, fp32 in (batch-major), fp16 out (node-major) ----
// 64-row x 64-col block tile, 256 threads, 4x4 micro-tile, packed FFMA2.
// K=128 staged into smem in two 64-deep chunks (smem budget 48KB).
__global__ void __launch_bounds__(256) k_gemm1(const float* __restrict__ x,
                                               const float* __restrict__ W,
                                               int rows, int N, int B) {
    __shared__ float ws[FIN * HID];   // 32KB, [k][col]
    __shared__ float xs[64 * 64];     // 16KB, [k][row_local] (k-major)
    int tid = threadIdx.x;
    int r0 = blockIdx.x * 64;

    for (int i = tid; i < FIN * HID / 4; i += 256)
        ((float4*)ws)[i] = ((const float4*)W)[i];

    int rl = tid & 63;          // row_local for staging
    int g  = tid >> 6;          // stage group 0..3
    int tx = tid & 15;          // col group: cols tx*4..+3
    int ty = tid >> 4;          // row group: rows ty*4..+3

    unsigned long long acc[4][2];
#pragma unroll
    for (int i = 0; i < 4; i++) { acc[i][0] = 0ull; acc[i][1] = 0ull; }

    int r_stage = r0 + rl;
    bool rv = (r_stage < rows);

    for (int ks = 0; ks < FIN; ks += 64) {
        __syncthreads();
        // stage xs[k - ks][rl]: each group loads 4 float4 chunks along k
#pragma unroll
        for (int c = 0; c < 4; c++) {
            int cc = g + c * 4;  // 0..15 float4 chunks covering 64 k
            float4 v = make_float4(0.f, 0.f, 0.f, 0.f);
            if (rv) v = *(const float4*)(x + (size_t)r_stage * FIN + ks + cc * 4);
            xs[(cc * 4 + 0) * 64 + rl] = v.x;
            xs[(cc * 4 + 1) * 64 + rl] = v.y;
            xs[(cc * 4 + 2) * 64 + rl] = v.z;
            xs[(cc * 4 + 3) * 64 + rl] = v.w;
        }
        __syncthreads();
#pragma unroll 4
        for (int k = 0; k < 64; k++) {
            ulonglong2 wp = *(const ulonglong2*)(ws + (ks + k) * HID + tx * 4);
            float4 xv = *(const float4*)(xs + k * 64 + ty * 4);
            unsigned long long x0 = dup2(xv.x), x1 = dup2(xv.y),
                               x2 = dup2(xv.z), x3 = dup2(xv.w);
            ffma2(acc[0][0], x0, wp.x); ffma2(acc[0][1], x0, wp.y);
            ffma2(acc[1][0], x1, wp.x); ffma2(acc[1][1], x1, wp.y);
            ffma2(acc[2][0], x2, wp.x); ffma2(acc[2][1], x2, wp.y);
            ffma2(acc[3][0], x3, wp.x); ffma2(acc[3][1], x3, wp.y);
        }
    }

#pragma unroll
    for (int i = 0; i < 4; i++) {
        int r = r0 + ty * 4 + i;
        if (r < rows) {
            int n = r % N, b = r / N;
            size_t orow = (size_t)n * B + b;
            float2 a0 = unpk(acc[i][0]);
            float2 a1 = unpk(acc[i][1]);
            __half2 h0 = __floats2half2_rn(a0.x, a0.y);
            __half2 h1 = __floats2half2_rn(a1.x, a1.y);
            uint2 st;
            st.x = *(unsigned int*)&h0;
            st.y = *(unsigned int*)&h1;
            *(uint2*)(g_hw + orow * HID + tx * 4) = st;
        }
    }
}

// ---------------- GEMM2: hw = h1 @ W2, fp16 in (node-major rows), fp16 out ----------
__global__ void __launch_bounds__(256) k_gemm2(const float* __restrict__ W, int rows) {
    __shared__ float ws[HID * HID];   // 16KB
    __shared__ float xs[64 * 64];     // 16KB, [k][row_local]
    int tid = threadIdx.x;
    int r0 = blockIdx.x * 64;

    for (int i = tid; i < HID * HID / 4; i += 256)
        ((float4*)ws)[i] = ((const float4*)W)[i];

    int rl = tid & 63;
    int g  = tid >> 6;
    int tx = tid & 15;
    int ty = tid >> 4;

    int r_stage = r0 + rl;
    bool rv = (r_stage < rows);
    // stage: K=64 halves = 128B per row; each group loads 2 x 16B chunks
#pragma unroll
    for (int c = 0; c < 2; c++) {
        int cc = g + c * 4;  // 0..7 chunks of 8 halves
        uint4 v = make_uint4(0u, 0u, 0u, 0u);
        if (rv) v = *(const uint4*)(g_h1 + (size_t)r_stage * HID + cc * 8);
        const __half2* hp = (const __half2*)&v;
#pragma unroll
        for (int j = 0; j < 4; j++) {
            float2 f = __half22float2(hp[j]);
            xs[(cc * 8 + j * 2 + 0) * 64 + rl] = f.x;
            xs[(cc * 8 + j * 2 + 1) * 64 + rl] = f.y;
        }
    }
    __syncthreads();

    unsigned long long acc[4][2];
#pragma unroll
    for (int i = 0; i < 4; i++) { acc[i][0] = 0ull; acc[i][1] = 0ull; }

#pragma unroll 4
    for (int k = 0; k < 64; k++) {
        ulonglong2 wp = *(const ulonglong2*)(ws + k * HID + tx * 4);
        float4 xv = *(const float4*)(xs + k * 64 + ty * 4);
        unsigned long long x0 = dup2(xv.x), x1 = dup2(xv.y),
                           x2 = dup2(xv.z), x3 = dup2(xv.w);
        ffma2(acc[0][0], x0, wp.x); ffma2(acc[0][1], x0, wp.y);
        ffma2(acc[1][0], x1, wp.x); ffma2(acc[1][1], x1, wp.y);
        ffma2(acc[2][0], x2, wp.x); ffma2(acc[2][1], x2, wp.y);
        ffma2(acc[3][0], x3, wp.x); ffma2(acc[3][1], x3, wp.y);
    }

#pragma unroll
    for (int i = 0; i < 4; i++) {
        int r = r0 + ty * 4 + i;
        if (r < rows) {
            float2 a0 = unpk(acc[i][0]);
            float2 a1 = unpk(acc[i][1]);
            __half2 h0 = __floats2half2_rn(a0.x, a0.y);
            __half2 h1 = __floats2half2_rn(a1.x, a1.y);
            uint2 st;
            st.x = *(unsigned int*)&h0;
            st.y = *(unsigned int*)&h1;
            *(uint2*)(g_hw + (size_t)r * HID + tx * 4) = st;
        }
    }
}

// ---------------- layer-1 aggregation + bias + relu -> g_h1 (fp16) ----------------
// One block per dst node; 256 threads cover 512 (b,h) values as half2 gathers.
__global__ void __launch_bounds__(256) k_agg1(const float* __restrict__ bias, int Bsz) {
    int node = blockIdx.x;
    int f = threadIdx.x * 2;
    int rowlen = Bsz * HID;
    if (f >= rowlen) return;
    int h = f & (HID - 1);
    float d = g_dis[node];
    float sn = d * d;
    size_t base = (size_t)node * rowlen;
    float2 v = __half22float2(*(const __half2*)(g_hw + base + f));
    float2 acc = make_float2(fmaf(v.x, sn, bias[h]), fmaf(v.y, sn, bias[h + 1]));

    int e = g_offs[node], e1 = g_offs[node + 1];
    for (; e + 1 < e1; e += 2) {
        int s0 = g_csr_src[e];
        int s1 = g_csr_src[e + 1];
        float w0 = g_csr_w[e];
        float w1 = g_csr_w[e + 1];
        float2 m0 = __half22float2(*(const __half2*)(g_hw + (size_t)s0 * rowlen + f));
        float2 m1 = __half22float2(*(const __half2*)(g_hw + (size_t)s1 * rowlen + f));
        acc.x = fmaf(w0, m0.x, acc.x);
        acc.y = fmaf(w0, m0.y, acc.y);
        acc.x = fmaf(w1, m1.x, acc.x);
        acc.y = fmaf(w1, m1.y, acc.y);
    }
    if (e < e1) {
        int s0 = g_csr_src[e];
        float w0 = g_csr_w[e];
        float2 m0 = __half22float2(*(const __half2*)(g_hw + (size_t)s0 * rowlen + f));
        acc.x = fmaf(w0, m0.x, acc.x);
        acc.y = fmaf(w0, m0.y, acc.y);
    }
    acc.x = fmaxf(acc.x, 0.f);
    acc.y = fmaxf(acc.y, 0.f);
    *(__half2*)(g_h1 + base + f) = __floats2half2_rn(acc.x, acc.y);
}

// ---------------- layer-2 aggregation + relu, fused fc dot + mean pool ----------------
__global__ void __launch_bounds__(256) k_agg2(const float* __restrict__ bias,
                                              const float* __restrict__ fcw, int Bsz) {
    int node = blockIdx.x;
    int f = threadIdx.x * 2;
    int rowlen = Bsz * HID;
    if (f >= rowlen) return;
    int h = f & (HID - 1);
    float d = g_dis[node];
    float sn = d * d;
    size_t base = (size_t)node * rowlen;
    float2 v = __half22float2(*(const __half2*)(g_hw + base + f));
    float2 acc = make_float2(fmaf(v.x, sn, bias[h]), fmaf(v.y, sn, bias[h + 1]));

    int e = g_offs[node], e1 = g_offs[node + 1];
    for (; e + 1 < e1; e += 2) {
        int s0 = g_csr_src[e];
        int s1 = g_csr_src[e + 1];
        float w0 = g_csr_w[e];
        float w1 = g_csr_w[e + 1];
        float2 m0 = __half22float2(*(const __half2*)(g_hw + (size_t)s0 * rowlen + f));
        float2 m1 = __half22float2(*(const __half2*)(g_hw + (size_t)s1 * rowlen + f));
        acc.x = fmaf(w0, m0.x, acc.x);
        acc.y = fmaf(w0, m0.y, acc.y);
        acc.x = fmaf(w1, m1.x, acc.x);
        acc.y = fmaf(w1, m1.y, acc.y);
    }
    if (e < e1) {
        int s0 = g_csr_src[e];
        float w0 = g_csr_w[e];
        float2 m0 = __half22float2(*(const __half2*)(g_hw + (size_t)s0 * rowlen + f));
        acc.x = fmaf(w0, m0.x, acc.x);
        acc.y = fmaf(w0, m0.y, acc.y);
    }
    acc.x = fmaxf(acc.x, 0.f);
    acc.y = fmaxf(acc.y, 0.f);

    float c = acc.x * fcw[h] + acc.y * fcw[h + 1];
#pragma unroll
    for (int o = 16; o; o >>= 1) c += __shfl_xor_sync(0xffffffffu, c, o);
    if ((threadIdx.x & 31) == 0) {
        int b = threadIdx.x >> 5;  // warp == batch
        atomicAdd(&g_partial[b * 64 + (node & 63)], c);
    }
}

// ---------------- final reduce ----------------
__global__ void k_final(float* __restrict__ out, const float* __restrict__ add,
                        const float* __restrict__ fcw, const float* __restrict__ fcb,
                        int N, int Bsz) {
    int b = threadIdx.x >> 5;
    int lane = threadIdx.x & 31;
    if (b < Bsz) {
        float s = g_partial[b * 64 + lane] + g_partial[b * 64 + 32 + lane];
#pragma unroll
        for (int o = 16; o; o >>= 1) s += __shfl_xor_sync(0xffffffffu, s, o);
        if (lane == 0)
            out[b] = s * (1.0f / (float)N) + add[b] * fcw[HID] + fcb[0];
    }
}

// ---------------- launch ----------------
extern "C" void kernel_launch(void* const* d_in, const int* in_sizes, int n_in,
                              void* d_out, int out_size) {
    const float* x   = (const float*)d_in[0];
    const float* add = (const float*)d_in[1];
    const int*   ei  = (const int*)d_in[2];
    const float* W1  = (const float*)d_in[3];
    const float* b1  = (const float*)d_in[4];
    const float* W2  = (const float*)d_in[5];
    const float* b2  = (const float*)d_in[6];
    const float* fcw = (const float*)d_in[7];
    const float* fcb = (const float*)d_in[8];
    float* out = (float*)d_out;

    int B = in_sizes[1];
    int E = in_sizes[2] / 2;
    int N = in_sizes[0] / (B * FIN);
    int rows = B * N;

    k_init<<<(N + 255) / 256, 256>>>(N);
    k_count<<<(E + 255) / 256, 256>>>(ei, E);
    k_scan<<<1, 1024>>>(N);
    k_csr<<<(E + 255) / 256, 256>>>(ei, E);

    k_gemm1<<<(rows + 63) / 64, 256>>>(x, W1, rows, N, B);
    k_agg1<<<N, 256>>>(b1, B);

    k_gemm2<<<(rows + 63) / 64, 256>>>(W2, rows);
    k_agg2<<<N, 256>>>(b2, fcw, B);

    k_final<<<1, 256>>>(out, add, fcw, fcb, N, B);
}

// round 3
// speedup vs baseline: 1.4591x; 1.2045x over previous
#include <cuda_runtime.h>
#include <cuda_fp16.h>
#include <cstdint>

#define MAXN 20000
#define MAXE 320000
#define FIN  128
#define HID  64
#define MAXB 8

// ---------------- static device scratch (allocation-free rule) ----------------
__device__ __half g_hw[(size_t)MAXN * MAXB * HID];  // transformed features, node-major [n][b*64], fp16
__device__ __half g_h1[(size_t)MAXN * MAXB * HID];  // layer-1 activations, node-major, fp16
__device__ int    g_cnt[MAXN];
__device__ int    g_offs[MAXN + 1];
__device__ int    g_cursor[MAXN];
__device__ float  g_dis[MAXN];
__device__ int    g_csr_src[MAXE];
__device__ float  g_csr_w[MAXE];
__device__ float  g_partial[MAXB * 64];

// ---------------- HMMA m16n8k16 fp16 -> fp32 ----------------
__device__ __forceinline__ void mma16816(float* c, uint32_t a0, uint32_t a1,
                                         uint32_t a2, uint32_t a3,
                                         uint32_t b0, uint32_t b1) {
    asm volatile(
        "mma.sync.aligned.m16n8k16.row.col.f32.f16.f16.f32 "
        "{%0,%1,%2,%3}, {%4,%5,%6,%7}, {%8,%9}, {%0,%1,%2,%3};"
        : "+f"(c[0]), "+f"(c[1]), "+f"(c[2]), "+f"(c[3])
        : "r"(a0), "r"(a1), "r"(a2), "r"(a3), "r"(b0), "r"(b1));
}

// ---------------- init ----------------
__global__ void k_init(int N) {
    int i = blockIdx.x * blockDim.x + threadIdx.x;
    if (i < N) g_cnt[i] = 0;
    if (i < MAXB * 64) g_partial[i] = 0.0f;
}

// ---------------- in-degree count ----------------
__global__ void k_count(const int* __restrict__ ei, int E) {
    int e = blockIdx.x * blockDim.x + threadIdx.x;
    if (e < E) atomicAdd(&g_cnt[ei[E + e]], 1);
}

// ---------------- single-block scan -> offsets, cursors, dis ----------------
__global__ void k_scan(int N) {
    __shared__ int ss[1024];
    int tid = threadIdx.x;
    int CH = (N + 1023) >> 10;
    int base = tid * CH;
    int s = 0;
    for (int j = 0; j < CH; j++) {
        int i = base + j;
        if (i < N) s += g_cnt[i];
    }
    ss[tid] = s;
    __syncthreads();
    for (int off = 1; off < 1024; off <<= 1) {
        int v = (tid >= off) ? ss[tid - off] : 0;
        __syncthreads();
        ss[tid] += v;
        __syncthreads();
    }
    int run = (tid == 0) ? 0 : ss[tid - 1];
    for (int j = 0; j < CH; j++) {
        int i = base + j;
        if (i < N) {
            g_offs[i] = run;
            g_cursor[i] = run;
            g_dis[i] = rsqrtf(1.0f + (float)g_cnt[i]);
            run += g_cnt[i];
        }
    }
    if (tid == 0) g_offs[N] = ss[1023];
}

// ---------------- CSR fill ----------------
__global__ void k_csr(const int* __restrict__ ei, int E) {
    int e = blockIdx.x * blockDim.x + threadIdx.x;
    if (e < E) {
        int s = ei[e];
        int d = ei[E + e];
        int pos = atomicAdd(&g_cursor[d], 1);
        g_csr_src[pos] = s;
        g_csr_w[pos] = g_dis[s] * g_dis[d];
    }
}

// ---------------- GEMM1 (HMMA): hw = x @ W1, fp32 in -> fp16 out (node-major) ----
// 64-row x 64-col block tile, 4 warps, each warp m16 x n64 (8 mma n-tiles).
// Xs/Wt row strides are 136 halves (68 4B-units, 68 mod 32 == 4): fragment
// loads (4*gid + tig) hit 32 distinct banks -> conflict-free.
#define XS1 136
__global__ void __launch_bounds__(128) k_gemm1(const float* __restrict__ x,
                                               const float* __restrict__ W,
                                               int rows, int N, int B) {
    __shared__ __align__(16) __half Xs[64 * XS1];
    __shared__ __align__(16) __half Wt[64 * XS1];
    int tid = threadIdx.x;
    size_t r0 = (size_t)blockIdx.x * 64;

    // Wt[n][k] = W1[k][n] (fp16)
    for (int idx = tid; idx < FIN * HID; idx += 128) {
        int k = idx >> 6, n = idx & 63;
        Wt[n * XS1 + k] = __float2half_rn(W[idx]);
    }
    // Xs[row][k] = x[r0+row][k] (fp16, converted)
    for (int idx = tid; idx < 64 * (FIN / 4); idx += 128) {
        int row = idx >> 5, c = idx & 31;
        size_t r = r0 + row;
        float4 v = make_float4(0.f, 0.f, 0.f, 0.f);
        if (r < (size_t)rows) v = *(const float4*)(x + r * FIN + c * 4);
        __half2* p = (__half2*)(Xs + row * XS1 + c * 4);
        p[0] = __floats2half2_rn(v.x, v.y);
        p[1] = __floats2half2_rn(v.z, v.w);
    }
    __syncthreads();

    int wid = tid >> 5, lane = tid & 31;
    int gid = lane >> 2, tig = lane & 3;
    const __half* A0 = Xs + (wid * 16 + gid) * XS1 + 2 * tig;
    const __half* A1 = A0 + 8 * XS1;

    float acc[8][4];
#pragma unroll
    for (int i = 0; i < 8; i++)
#pragma unroll
        for (int j = 0; j < 4; j++) acc[i][j] = 0.f;

#pragma unroll
    for (int ks = 0; ks < FIN / 16; ks++) {
        int k0 = ks * 16;
        uint32_t a0 = *(const uint32_t*)(A0 + k0);
        uint32_t a1 = *(const uint32_t*)(A1 + k0);
        uint32_t a2 = *(const uint32_t*)(A0 + k0 + 8);
        uint32_t a3 = *(const uint32_t*)(A1 + k0 + 8);
#pragma unroll
        for (int nt = 0; nt < 8; nt++) {
            const __half* Bp = Wt + (nt * 8 + gid) * XS1 + k0 + 2 * tig;
            uint32_t b0 = *(const uint32_t*)(Bp);
            uint32_t b1 = *(const uint32_t*)(Bp + 8);
            mma16816(acc[nt], a0, a1, a2, a3, b0, b1);
        }
    }

    // epilogue: remap row r = b*N+n -> node-major n*B+b, write fp16
    size_t r1 = r0 + wid * 16 + gid;
    size_t r2 = r1 + 8;
    if (r1 < (size_t)rows) {
        int n = (int)(r1 % N), b = (int)(r1 / N);
        __half* o = g_hw + ((size_t)n * B + b) * HID + 2 * tig;
#pragma unroll
        for (int nt = 0; nt < 8; nt++)
            *(__half2*)(o + nt * 8) = __floats2half2_rn(acc[nt][0], acc[nt][1]);
    }
    if (r2 < (size_t)rows) {
        int n = (int)(r2 % N), b = (int)(r2 / N);
        __half* o = g_hw + ((size_t)n * B + b) * HID + 2 * tig;
#pragma unroll
        for (int nt = 0; nt < 8; nt++)
            *(__half2*)(o + nt * 8) = __floats2half2_rn(acc[nt][2], acc[nt][3]);
    }
}

// ---------------- GEMM2 (HMMA): hw = h1 @ W2, fp16 in (node-major) -> fp16 out ----
// Row stride 72 halves (36 units, 36 mod 32 == 4) -> conflict-free fragments.
#define XS2 72
__global__ void __launch_bounds__(128) k_gemm2(const float* __restrict__ W, int rows) {
    __shared__ __align__(16) __half Xs[64 * XS2];
    __shared__ __align__(16) __half Wt[64 * XS2];
    int tid = threadIdx.x;
    size_t r0 = (size_t)blockIdx.x * 64;

    for (int idx = tid; idx < HID * HID; idx += 128) {
        int k = idx >> 6, n = idx & 63;
        Wt[n * XS2 + k] = __float2half_rn(W[idx]);
    }
    for (int idx = tid; idx < 64 * (HID / 8); idx += 128) {
        int row = idx >> 3, c = idx & 7;
        size_t r = r0 + row;
        uint4 v = make_uint4(0u, 0u, 0u, 0u);
        if (r < (size_t)rows) v = *(const uint4*)(g_h1 + r * HID + c * 8);
        *(uint4*)(Xs + row * XS2 + c * 8) = v;
    }
    __syncthreads();

    int wid = tid >> 5, lane = tid & 31;
    int gid = lane >> 2, tig = lane & 3;
    const __half* A0 = Xs + (wid * 16 + gid) * XS2 + 2 * tig;
    const __half* A1 = A0 + 8 * XS2;

    float acc[8][4];
#pragma unroll
    for (int i = 0; i < 8; i++)
#pragma unroll
        for (int j = 0; j < 4; j++) acc[i][j] = 0.f;

#pragma unroll
    for (int ks = 0; ks < HID / 16; ks++) {
        int k0 = ks * 16;
        uint32_t a0 = *(const uint32_t*)(A0 + k0);
        uint32_t a1 = *(const uint32_t*)(A1 + k0);
        uint32_t a2 = *(const uint32_t*)(A0 + k0 + 8);
        uint32_t a3 = *(const uint32_t*)(A1 + k0 + 8);
#pragma unroll
        for (int nt = 0; nt < 8; nt++) {
            const __half* Bp = Wt + (nt * 8 + gid) * XS2 + k0 + 2 * tig;
            uint32_t b0 = *(const uint32_t*)(Bp);
            uint32_t b1 = *(const uint32_t*)(Bp + 8);
            mma16816(acc[nt], a0, a1, a2, a3, b0, b1);
        }
    }

    // rows already node-major; write straight back
    size_t r1 = r0 + wid * 16 + gid;
    size_t r2 = r1 + 8;
    if (r1 < (size_t)rows) {
        __half* o = g_hw + r1 * HID + 2 * tig;
#pragma unroll
        for (int nt = 0; nt < 8; nt++)
            *(__half2*)(o + nt * 8) = __floats2half2_rn(acc[nt][0], acc[nt][1]);
    }
    if (r2 < (size_t)rows) {
        __half* o = g_hw + r2 * HID + 2 * tig;
#pragma unroll
        for (int nt = 0; nt < 8; nt++)
            *(__half2*)(o + nt * 8) = __floats2half2_rn(acc[nt][2], acc[nt][3]);
    }
}

// ---------------- layer-1 aggregation + bias + relu -> g_h1 (fp16) ----------------
__global__ void __launch_bounds__(256) k_agg1(const float* __restrict__ bias, int Bsz) {
    int node = blockIdx.x;
    int f = threadIdx.x * 2;
    int rowlen = Bsz * HID;
    if (f >= rowlen) return;
    int h = f & (HID - 1);
    float d = g_dis[node];
    float sn = d * d;
    size_t base = (size_t)node * rowlen;
    float2 v = __half22float2(*(const __half2*)(g_hw + base + f));
    float2 acc = make_float2(fmaf(v.x, sn, bias[h]), fmaf(v.y, sn, bias[h + 1]));

    int e = g_offs[node], e1 = g_offs[node + 1];
    for (; e + 1 < e1; e += 2) {
        int s0 = g_csr_src[e];
        int s1 = g_csr_src[e + 1];
        float w0 = g_csr_w[e];
        float w1 = g_csr_w[e + 1];
        float2 m0 = __half22float2(*(const __half2*)(g_hw + (size_t)s0 * rowlen + f));
        float2 m1 = __half22float2(*(const __half2*)(g_hw + (size_t)s1 * rowlen + f));
        acc.x = fmaf(w0, m0.x, acc.x);
        acc.y = fmaf(w0, m0.y, acc.y);
        acc.x = fmaf(w1, m1.x, acc.x);
        acc.y = fmaf(w1, m1.y, acc.y);
    }
    if (e < e1) {
        int s0 = g_csr_src[e];
        float w0 = g_csr_w[e];
        float2 m0 = __half22float2(*(const __half2*)(g_hw + (size_t)s0 * rowlen + f));
        acc.x = fmaf(w0, m0.x, acc.x);
        acc.y = fmaf(w0, m0.y, acc.y);
    }
    acc.x = fmaxf(acc.x, 0.f);
    acc.y = fmaxf(acc.y, 0.f);
    *(__half2*)(g_h1 + base + f) = __floats2half2_rn(acc.x, acc.y);
}

// ---------------- layer-2 aggregation + relu, fused fc dot + mean pool ----------------
__global__ void __launch_bounds__(256) k_agg2(const float* __restrict__ bias,
                                              const float* __restrict__ fcw, int Bsz) {
    int node = blockIdx.x;
    int f = threadIdx.x * 2;
    int rowlen = Bsz * HID;
    if (f >= rowlen) return;
    int h = f & (HID - 1);
    float d = g_dis[node];
    float sn = d * d;
    size_t base = (size_t)node * rowlen;
    float2 v = __half22float2(*(const __half2*)(g_hw + base + f));
    float2 acc = make_float2(fmaf(v.x, sn, bias[h]), fmaf(v.y, sn, bias[h + 1]));

    int e = g_offs[node], e1 = g_offs[node + 1];
    for (; e + 1 < e1; e += 2) {
        int s0 = g_csr_src[e];
        int s1 = g_csr_src[e + 1];
        float w0 = g_csr_w[e];
        float w1 = g_csr_w[e + 1];
        float2 m0 = __half22float2(*(const __half2*)(g_hw + (size_t)s0 * rowlen + f));
        float2 m1 = __half22float2(*(const __half2*)(g_hw + (size_t)s1 * rowlen + f));
        acc.x = fmaf(w0, m0.x, acc.x);
        acc.y = fmaf(w0, m0.y, acc.y);
        acc.x = fmaf(w1, m1.x, acc.x);
        acc.y = fmaf(w1, m1.y, acc.y);
    }
    if (e < e1) {
        int s0 = g_csr_src[e];
        float w0 = g_csr_w[e];
        float2 m0 = __half22float2(*(const __half2*)(g_hw + (size_t)s0 * rowlen + f));
        acc.x = fmaf(w0, m0.x, acc.x);
        acc.y = fmaf(w0, m0.y, acc.y);
    }
    acc.x = fmaxf(acc.x, 0.f);
    acc.y = fmaxf(acc.y, 0.f);

    float c = acc.x * fcw[h] + acc.y * fcw[h + 1];
#pragma unroll
    for (int o = 16; o; o >>= 1) c += __shfl_xor_sync(0xffffffffu, c, o);
    if ((threadIdx.x & 31) == 0) {
        int b = threadIdx.x >> 5;  // warp == batch
        atomicAdd(&g_partial[b * 64 + (node & 63)], c);
    }
}

// ---------------- final reduce ----------------
__global__ void k_final(float* __restrict__ out, const float* __restrict__ add,
                        const float* __restrict__ fcw, const float* __restrict__ fcb,
                        int N, int Bsz) {
    int b = threadIdx.x >> 5;
    int lane = threadIdx.x & 31;
    if (b < Bsz) {
        float s = g_partial[b * 64 + lane] + g_partial[b * 64 + 32 + lane];
#pragma unroll
        for (int o = 16; o; o >>= 1) s += __shfl_xor_sync(0xffffffffu, s, o);
        if (lane == 0)
            out[b] = s * (1.0f / (float)N) + add[b] * fcw[HID] + fcb[0];
    }
}

// ---------------- launch ----------------
extern "C" void kernel_launch(void* const* d_in, const int* in_sizes, int n_in,
                              void* d_out, int out_size) {
    const float* x   = (const float*)d_in[0];
    const float* add = (const float*)d_in[1];
    const int*   ei  = (const int*)d_in[2];
    const float* W1  = (const float*)d_in[3];
    const float* b1  = (const float*)d_in[4];
    const float* W2  = (const float*)d_in[5];
    const float* b2  = (const float*)d_in[6];
    const float* fcw = (const float*)d_in[7];
    const float* fcb = (const float*)d_in[8];
    float* out = (float*)d_out;

    int B = in_sizes[1];
    int E = in_sizes[2] / 2;
    int N = in_sizes[0] / (B * FIN);
    int rows = B * N;

    k_init<<<(N + 255) / 256, 256>>>(N);
    k_count<<<(E + 255) / 256, 256>>>(ei, E);
    k_scan<<<1, 1024>>>(N);
    k_csr<<<(E + 255) / 256, 256>>>(ei, E);

    k_gemm1<<<(rows + 63) / 64, 128>>>(x, W1, rows, N, B);
    k_agg1<<<N, 256>>>(b1, B);

    k_gemm2<<<(rows + 63) / 64, 128>>>(W2, rows);
    k_agg2<<<N, 256>>>(b2, fcw, B);

    k_final<<<1, 256>>>(out, add, fcw, fcb, N, B);
}